// round 12
// baseline (speedup 1.0000x reference)
#include <cuda_runtime.h>

#define B_   8
#define N_   1024
#define C_   512
#define H_   8
#define D_   64
#define TOPK 16
#define M_   (B_ * N_)          // 8192 rows
#define KV_C (2 * C_)           // 1024
#define NROWS ((size_t)B_ * H_ * N_)   // 65536 score rows

// Scratch (device globals; no allocation allowed)
__device__ float g_q[M_ * C_];          // relu(x@Wq+bq)
__device__ float g_kv[M_ * KV_C];       // x@Wkv+bkv  (k at [0,512), v at [512,1024))
__device__ float g_att[M_ * C_];        // attention output (pre-projection)
__device__ float g_vsum[B_ * H_ * D_];  // per-(b,h) column sums of v
__device__ unsigned g_su[NROWS * N_];   // mono-packed scores, 256MB

// ---------------------------------------------------------------------------
// Packed fp32x2 helpers (sm_103a FFMA2 — each half rounds exactly like FFMA).
// ---------------------------------------------------------------------------
typedef unsigned long long u64t;

__device__ __forceinline__ void ffma2(u64t& d, u64t a, u64t b)
{
    asm("fma.rn.f32x2 %0, %1, %2, %0;" : "+l"(d) : "l"(a), "l"(b));
}
__device__ __forceinline__ u64t pack2(float lo, float hi)
{
    u64t r; asm("mov.b64 %0, {%1, %2};" : "=l"(r) : "f"(lo), "f"(hi)); return r;
}
__device__ __forceinline__ float2 unpack2(u64t p)
{
    float lo, hi; asm("mov.b64 {%0, %1}, %2;" : "=f"(lo), "=f"(hi) : "l"(p));
    return make_float2(lo, hi);
}

// ---------------------------------------------------------------------------
// Tiled fp32 GEMM via FFMA2: C = act(A[M,K] @ W[K,Nc] + bias), 128x128 tile,
// BK=8, 256 threads, 8x8 microtile (4 row-pairs x 8 cols packed).
// ---------------------------------------------------------------------------
template <bool RELU>
__global__ __launch_bounds__(256) void gemm_kernel(
    const float* __restrict__ A, const float* __restrict__ W,
    const float* __restrict__ bias, float* __restrict__ Cc, int K, int Nc)
{
    __shared__ float As[8][132];   // transposed A tile (As[k][row]); 132*4 % 8 == 0
    __shared__ float Bs[8][128];

    int tid = threadIdx.x;
    int tx  = tid & 15;
    int ty  = tid >> 4;
    int rowTile = blockIdx.y * 128;
    int colTile = blockIdx.x * 128;

    int arow = tid >> 1;
    int aseg = (tid & 1) * 4;
    int bkr  = tid >> 5;
    int bcol = (tid & 31) * 4;

    const float* Aptr = A + (size_t)(rowTile + arow) * K + aseg;
    const float* Bptr = W + (size_t)bkr * Nc + colTile + bcol;

    u64t acc2[4][8];               // [row-pair][col], rows ty*8+2p, ty*8+2p+1
#pragma unroll
    for (int p = 0; p < 4; p++)
#pragma unroll
        for (int j = 0; j < 8; j++) acc2[p][j] = 0ull;   // (0.f, 0.f)

    for (int kt = 0; kt < K; kt += 8) {
        float4 av = *(const float4*)(Aptr + kt);
        float4 bv = *(const float4*)(Bptr + (size_t)kt * Nc);
        As[aseg + 0][arow] = av.x;
        As[aseg + 1][arow] = av.y;
        As[aseg + 2][arow] = av.z;
        As[aseg + 3][arow] = av.w;
        *(float4*)&Bs[bkr][bcol] = bv;
        __syncthreads();
#pragma unroll
        for (int kk = 0; kk < 8; kk++) {
            // row-pairs straight from shared as 64-bit loads (ty*8 even -> 8B aligned)
            u64t ap[4];
#pragma unroll
            for (int p = 0; p < 4; p++)
                ap[p] = *(const u64t*)&As[kk][ty * 8 + 2 * p];
            float b[8];
            *(float4*)(b)     = *(const float4*)&Bs[kk][tx * 8];
            *(float4*)(b + 4) = *(const float4*)&Bs[kk][tx * 8 + 4];
            u64t bb[8];
#pragma unroll
            for (int j = 0; j < 8; j++) bb[j] = pack2(b[j], b[j]);
#pragma unroll
            for (int p = 0; p < 4; p++)
#pragma unroll
                for (int j = 0; j < 8; j++)
                    ffma2(acc2[p][j], ap[p], bb[j]);
        }
        __syncthreads();
    }

    // epilogue: unpack row-pairs, add bias, optional relu
#pragma unroll
    for (int p = 0; p < 4; p++) {
        float r0[8], r1[8];
#pragma unroll
        for (int j = 0; j < 8; j++) {
            float2 v = unpack2(acc2[p][j]);
            r0[j] = v.x + bias[colTile + tx * 8 + j];
            r1[j] = v.y + bias[colTile + tx * 8 + j];
            if (RELU) { r0[j] = fmaxf(r0[j], 0.f); r1[j] = fmaxf(r1[j], 0.f); }
        }
        float* c0 = Cc + (size_t)(rowTile + ty * 8 + 2 * p) * Nc + colTile + tx * 8;
        float* c1 = c0 + Nc;
        *(float4*)(c0)     = make_float4(r0[0], r0[1], r0[2], r0[3]);
        *(float4*)(c0 + 4) = make_float4(r0[4], r0[5], r0[6], r0[7]);
        *(float4*)(c1)     = make_float4(r1[0], r1[1], r1[2], r1[3]);
        *(float4*)(c1 + 4) = make_float4(r1[4], r1[5], r1[6], r1[7]);
    }
}

// ---------------------------------------------------------------------------
// vsum[b,h,d] = sum_n v[b,h,n,d]
// ---------------------------------------------------------------------------
__global__ __launch_bounds__(256) void vsum_kernel(float* __restrict__ vs)
{
    __shared__ float red[256];
    int bh = blockIdx.x;
    int b = bh >> 3, h = bh & 7;
    int tid = threadIdx.x;
    int d = tid & 63, chunk = tid >> 6;

    size_t base = ((size_t)b * N_) * KV_C + C_ + (size_t)h * D_ + d;
    float s = 0.f;
    int n0 = chunk * 256;
    for (int n = n0; n < n0 + 256; n++)
        s += g_kv[base + (size_t)n * KV_C];
    red[tid] = s;
    __syncthreads();
    if (chunk == 0)
        vs[bh * 64 + d] = red[d] + red[d + 64] + red[d + 128] + red[d + 192];
}

// ---------------------------------------------------------------------------
// Full-precision monotonic float<->uint mapping (bijective, order-preserving).
// ---------------------------------------------------------------------------
__device__ __forceinline__ unsigned mono_pack(float s)
{
    unsigned b = __float_as_uint(s);
    return b ^ (unsigned)(((int)b >> 31) | 0x80000000);
}
__device__ __forceinline__ float mono_unpack(unsigned u)
{
    unsigned b = (u & 0x80000000u) ? (u ^ 0x80000000u) : ~u;
    return __uint_as_float(b);
}

// ---------------------------------------------------------------------------
// scores_kernel: 64 q-rows x 1024 keys per block, FFMA2 inner product.
// Per warp 8 rows (4 packed row-pairs) x 4 cols. qT row-pairs load directly
// as LDS.64; k cols duplicated into both halves. 2 blocks/SM.
// QT_PITCH must be EVEN (8B-aligned u64 loads).
// ---------------------------------------------------------------------------
#define SROWS 64
#define QT_PITCH 66
#define KST_PITCH 132
#define SC_SMEM_BYTES ((64 * QT_PITCH + 64 * KST_PITCH) * 4)

__global__ __launch_bounds__(256, 2) void scores_kernel()
{
    extern __shared__ float sm[];
    float* qT  = sm;                    // [64][66]  qT[d][r]
    float* kst = qT + 64 * QT_PITCH;    // [64][132] kst[d][m]

    int bh = blockIdx.y;
    int b = bh >> 3, h = bh & 7;
    int n0 = blockIdx.x * SROWS;
    int tid = threadIdx.x;
    int w    = tid >> 5;                // warp 0..7 -> rows 8w..8w+7
    int lane = tid & 31;                // cols 4*lane..4*lane+3 per tile
    const float scale = 0.125f;

    // load 64 q rows transposed (coalesced LDG)
    {
        size_t qbase = ((size_t)(b * N_ + n0)) * C_ + (size_t)h * D_;
        for (int f = tid; f < SROWS * 64; f += 256) {
            int r = f >> 6, d = f & 63;
            qT[d * QT_PITCH + r] = g_q[qbase + (size_t)r * C_ + d];
        }
    }

    size_t kbase = ((size_t)b * N_) * KV_C + (size_t)h * D_;
    size_t rowbase = ((size_t)bh * N_ + n0);

    // k tile: 128 keys x 64 d -> 8 float4 per thread
    float4 pf[8];
#pragma unroll
    for (int i = 0; i < 8; i++) {
        int g = tid + 256 * i;
        int m = g & 127, d4 = (g >> 7) * 4;
        pf[i] = *(const float4*)&g_kv[kbase + (size_t)m * KV_C + d4];
    }

    for (int mt = 0; mt < N_; mt += 128) {
        __syncthreads();
#pragma unroll
        for (int i = 0; i < 8; i++) {
            int g = tid + 256 * i;
            int m = g & 127, d4 = (g >> 7) * 4;
            kst[(d4 + 0) * KST_PITCH + m] = pf[i].x;   // lanes->consecutive m: cf-free
            kst[(d4 + 1) * KST_PITCH + m] = pf[i].y;
            kst[(d4 + 2) * KST_PITCH + m] = pf[i].z;
            kst[(d4 + 3) * KST_PITCH + m] = pf[i].w;
        }
        __syncthreads();

        if (mt + 128 < N_) {
#pragma unroll
            for (int i = 0; i < 8; i++) {
                int g = tid + 256 * i;
                int m = g & 127, d4 = (g >> 7) * 4;
                pf[i] = *(const float4*)&g_kv[kbase + (size_t)(mt + 128 + m) * KV_C + d4];
            }
        }

        u64t acc2[4][4];               // [row-pair][col]
#pragma unroll
        for (int p = 0; p < 4; p++)
#pragma unroll
            for (int c = 0; c < 4; c++) acc2[p][c] = 0ull;

        const float* qTw = qT + 8 * w;          // even offset -> 8B aligned
#pragma unroll 4
        for (int d = 0; d < 64; d++) {
            float4 k4 = *(const float4*)&kst[d * KST_PITCH + 4 * lane];
            u64t kb[4];
            kb[0] = pack2(k4.x, k4.x); kb[1] = pack2(k4.y, k4.y);
            kb[2] = pack2(k4.z, k4.z); kb[3] = pack2(k4.w, k4.w);
            u64t qp[4];
#pragma unroll
            for (int p = 0; p < 4; p++)
                qp[p] = *(const u64t*)&qTw[d * QT_PITCH + 2 * p];  // row-pair broadcast
#pragma unroll
            for (int p = 0; p < 4; p++)
#pragma unroll
                for (int c = 0; c < 4; c++)
                    ffma2(acc2[p][c], qp[p], kb[c]);
        }

#pragma unroll
        for (int p = 0; p < 4; p++) {
            float2 v0 = unpack2(acc2[p][0]);
            float2 v1 = unpack2(acc2[p][1]);
            float2 v2 = unpack2(acc2[p][2]);
            float2 v3 = unpack2(acc2[p][3]);
            uint4 pk;
            pk.x = mono_pack(v0.x * scale); pk.y = mono_pack(v1.x * scale);
            pk.z = mono_pack(v2.x * scale); pk.w = mono_pack(v3.x * scale);
            *(uint4*)&g_su[(rowbase + 8 * w + 2 * p) * N_ + mt + 4 * lane] = pk;
            pk.x = mono_pack(v0.y * scale); pk.y = mono_pack(v1.y * scale);
            pk.z = mono_pack(v2.y * scale); pk.w = mono_pack(v3.y * scale);
            *(uint4*)&g_su[(rowbase + 8 * w + 2 * p + 1) * N_ + mt + 4 * lane] = pk;
        }
    }
}

// ---------------------------------------------------------------------------
// topk_kernel: 1 warp per score row, 8 rows/block, no smem. uint4 score
// loads, exact uint-argmax top-16 (indices/weights in registers, shfl
// broadcast), closed-form sparse softmax, float2 gather epilogue.
// ---------------------------------------------------------------------------
__global__ __launch_bounds__(256) void topk_kernel(const float* __restrict__ vs)
{
    size_t row = (size_t)blockIdx.x * 8 + (threadIdx.x >> 5);
    int lane = threadIdx.x & 31;
    int bh = (int)(row >> 10);
    int n  = (int)(row & 1023);
    int b = bh >> 3, h = bh & 7;

    const unsigned* srow = g_su + row * N_;

    // load 1024 scores as 8 uint4/lane; slot j=(i*4+c) <-> col 4*lane+128*i+c
    unsigned v[32];
#pragma unroll
    for (int i = 0; i < 8; i++) {
        uint4 p = *(const uint4*)&srow[4 * lane + 128 * i];
        v[4 * i + 0] = (p.x & ~31u) | (unsigned)(4 * i + 0);
        v[4 * i + 1] = (p.y & ~31u) | (unsigned)(4 * i + 1);
        v[4 * i + 2] = (p.z & ~31u) | (unsigned)(4 * i + 2);
        v[4 * i + 3] = (p.w & ~31u) | (unsigned)(4 * i + 3);
    }

    int selidx = 0;
#pragma unroll
    for (int it = 0; it < TOPK; it++) {
        unsigned lm = v[0];
#pragma unroll
        for (int j = 1; j < 32; j++) lm = max(lm, v[j]);
        unsigned gm = __reduce_max_sync(0xffffffffu, lm);
        unsigned ball = __ballot_sync(0xffffffffu, lm == gm);
        int wl = __ffs(ball) - 1;
        int jj = (int)(gm & 31u);
        if (lane == it)
            selidx = 4 * wl + 128 * (jj >> 2) + (jj & 3);
        if (lane == wl) {
#pragma unroll
            for (int j = 0; j < 32; j++)
                if (j == jj) v[j] = 0u;
        }
    }

    // exact-score closed-form sparse softmax
    float sv = 0.f;
    if (lane < TOPK) sv = mono_unpack(srow[selidx]);
    float s0 = __shfl_sync(0xffffffffu, sv, 0);
    float Mx = fmaxf(0.f, s0);
    float c  = expf(-Mx);
    float ww = (lane < TOPK) ? expf(sv - Mx) : 0.f;
    float s = ww;
#pragma unroll
    for (int off = 16; off; off >>= 1)
        s += __shfl_xor_sync(0xffffffffu, s, off);
    float Z = s + (float)(N_ - TOPK) * c;
    float wfin = (ww - c) / Z;
    float cz = c / Z;

    // gather epilogue: each lane owns d = {2*lane, 2*lane+1}
    size_t vbase = ((size_t)b * N_) * KV_C + C_ + (size_t)h * D_ + 2 * lane;
    float2 o = make_float2(0.f, 0.f);
#pragma unroll
    for (int i = 0; i < TOPK; i++) {
        float wi = __shfl_sync(0xffffffffu, wfin, i);
        int   ii = __shfl_sync(0xffffffffu, selidx, i);
        float2 vv = *(const float2*)&g_kv[vbase + (size_t)ii * KV_C];
        o.x += wi * vv.x; o.y += wi * vv.y;
    }
    float2 sv2 = *(const float2*)&vs[bh * 64 + 2 * lane];
    o.x += cz * sv2.x; o.y += cz * sv2.y;
    *(float2*)&g_att[((size_t)(b * N_ + n)) * C_ + (size_t)h * D_ + 2 * lane] = o;
}

// ---------------------------------------------------------------------------
extern "C" void kernel_launch(void* const* d_in, const int* in_sizes, int n_in,
                              void* d_out, int out_size)
{
    const float* x   = (const float*)d_in[0];
    const float* Wq  = (const float*)d_in[1];
    const float* bq  = (const float*)d_in[2];
    const float* Wkv = (const float*)d_in[3];
    const float* bkv = (const float*)d_in[4];
    const float* Wp  = (const float*)d_in[5];
    const float* bp  = (const float*)d_in[6];
    float* out = (float*)d_out;

    float *gq, *gkv, *gatt, *gvs;
    cudaGetSymbolAddress((void**)&gq,  g_q);
    cudaGetSymbolAddress((void**)&gkv, g_kv);
    cudaGetSymbolAddress((void**)&gatt, g_att);
    cudaGetSymbolAddress((void**)&gvs, g_vsum);

    // 1. Q = relu(x @ Wq + bq)
    gemm_kernel<true><<<dim3(C_ / 128, M_ / 128), 256>>>(x, Wq, bq, gq, C_, C_);
    // 2. KV = x @ Wkv + bkv
    gemm_kernel<false><<<dim3(KV_C / 128, M_ / 128), 256>>>(x, Wkv, bkv, gkv, C_, KV_C);
    // 3. vsum
    vsum_kernel<<<B_ * H_, 256>>>(gvs);
    // 4. scores GEMM -> packed global buffer
    cudaFuncSetAttribute(scores_kernel, cudaFuncAttributeMaxDynamicSharedMemorySize,
                         SC_SMEM_BYTES);
    scores_kernel<<<dim3(N_ / SROWS, B_ * H_), 256, SC_SMEM_BYTES>>>();
    // 5. top-16 + sparse softmax + gather
    topk_kernel<<<(int)(NROWS / 8), 256>>>(gvs);
    // 6. out = att @ Wp + bp
    gemm_kernel<false><<<dim3(C_ / 128, M_ / 128), 256>>>(gatt, Wp, bp, out, C_, C_);
}

// round 16
// speedup vs baseline: 1.0817x; 1.0817x over previous
#include <cuda_runtime.h>

#define B_   8
#define N_   1024
#define C_   512
#define H_   8
#define D_   64
#define TOPK 16
#define M_   (B_ * N_)          // 8192 rows
#define KV_C (2 * C_)           // 1024
#define NROWS ((size_t)B_ * H_ * N_)   // 65536 score rows

// Scratch (device globals; no allocation allowed)
__device__ float g_q[M_ * C_];          // relu(x@Wq+bq)
__device__ float g_kv[M_ * KV_C];       // x@Wkv+bkv  (k at [0,512), v at [512,1024))
__device__ float g_att[M_ * C_];        // attention output (pre-projection)
__device__ float g_vsum[B_ * H_ * D_];  // per-(b,h) column sums of v
__device__ unsigned g_su[NROWS * N_];   // mono-packed scores, 256MB

// ---------------------------------------------------------------------------
// Tiled fp32 GEMM, double-buffered smem (one barrier per k-tile):
// C = act(A[M,K] @ W[K,Nc] + bias), 128x128 tile, BK=8, 8x8 microtile.
// ---------------------------------------------------------------------------
template <bool RELU>
__global__ __launch_bounds__(256, 2) void gemm_kernel(
    const float* __restrict__ A, const float* __restrict__ W,
    const float* __restrict__ bias, float* __restrict__ Cc, int K, int Nc)
{
    __shared__ float As[2][8][132];
    __shared__ float Bs[2][8][128];

    int tid = threadIdx.x;
    int tx  = tid & 15;
    int ty  = tid >> 4;
    int rowTile = blockIdx.y * 128;
    int colTile = blockIdx.x * 128;

    int arow = tid >> 1;
    int aseg = (tid & 1) * 4;
    int bkr  = tid >> 5;
    int bcol = (tid & 31) * 4;

    const float* Aptr = A + (size_t)(rowTile + arow) * K + aseg;
    const float* Bptr = W + (size_t)bkr * Nc + colTile + bcol;

    float acc[8][8];
#pragma unroll
    for (int i = 0; i < 8; i++)
#pragma unroll
        for (int j = 0; j < 8; j++) acc[i][j] = 0.f;

    // prologue: stage tile 0, prefetch tile 1 into registers
    float4 av = *(const float4*)(Aptr);
    float4 bv = *(const float4*)(Bptr);
    As[0][aseg + 0][arow] = av.x;
    As[0][aseg + 1][arow] = av.y;
    As[0][aseg + 2][arow] = av.z;
    As[0][aseg + 3][arow] = av.w;
    *(float4*)&Bs[0][bkr][bcol] = bv;
    if (8 < K) {
        av = *(const float4*)(Aptr + 8);
        bv = *(const float4*)(Bptr + (size_t)8 * Nc);
    }
    __syncthreads();

    int cur = 0;
    for (int kt = 0; kt < K; kt += 8) {
        if (kt + 8 < K) {
            // stage tile kt+8 into the other buffer (safe: prior sync drained reads)
            As[cur ^ 1][aseg + 0][arow] = av.x;
            As[cur ^ 1][aseg + 1][arow] = av.y;
            As[cur ^ 1][aseg + 2][arow] = av.z;
            As[cur ^ 1][aseg + 3][arow] = av.w;
            *(float4*)&Bs[cur ^ 1][bkr][bcol] = bv;
            if (kt + 16 < K) {   // prefetch tile kt+16 (overlaps compute below)
                av = *(const float4*)(Aptr + kt + 16);
                bv = *(const float4*)(Bptr + (size_t)(kt + 16) * Nc);
            }
        }
#pragma unroll
        for (int kk = 0; kk < 8; kk++) {
            float a[8], b[8];
            *(float4*)(a)     = *(const float4*)&As[cur][kk][ty * 8];
            *(float4*)(a + 4) = *(const float4*)&As[cur][kk][ty * 8 + 4];
            *(float4*)(b)     = *(const float4*)&Bs[cur][kk][tx * 8];
            *(float4*)(b + 4) = *(const float4*)&Bs[cur][kk][tx * 8 + 4];
#pragma unroll
            for (int i = 0; i < 8; i++)
#pragma unroll
                for (int j = 0; j < 8; j++)
                    acc[i][j] += a[i] * b[j];
        }
        __syncthreads();
        cur ^= 1;
    }

#pragma unroll
    for (int i = 0; i < 8; i++) {
        float* crow = Cc + (size_t)(rowTile + ty * 8 + i) * Nc + colTile + tx * 8;
#pragma unroll
        for (int j = 0; j < 8; j += 4) {
            float4 o;
            o.x = acc[i][j + 0] + bias[colTile + tx * 8 + j + 0];
            o.y = acc[i][j + 1] + bias[colTile + tx * 8 + j + 1];
            o.z = acc[i][j + 2] + bias[colTile + tx * 8 + j + 2];
            o.w = acc[i][j + 3] + bias[colTile + tx * 8 + j + 3];
            if (RELU) {
                o.x = fmaxf(o.x, 0.f); o.y = fmaxf(o.y, 0.f);
                o.z = fmaxf(o.z, 0.f); o.w = fmaxf(o.w, 0.f);
            }
            *(float4*)(crow + j) = o;
        }
    }
}

// ---------------------------------------------------------------------------
// vsum[b,h,d] = sum_n v[b,h,n,d]
// ---------------------------------------------------------------------------
__global__ __launch_bounds__(256) void vsum_kernel(float* __restrict__ vs)
{
    __shared__ float red[256];
    int bh = blockIdx.x;
    int b = bh >> 3, h = bh & 7;
    int tid = threadIdx.x;
    int d = tid & 63, chunk = tid >> 6;

    size_t base = ((size_t)b * N_) * KV_C + C_ + (size_t)h * D_ + d;
    float s = 0.f;
    int n0 = chunk * 256;
    for (int n = n0; n < n0 + 256; n++)
        s += g_kv[base + (size_t)n * KV_C];
    red[tid] = s;
    __syncthreads();
    if (chunk == 0)
        vs[bh * 64 + d] = red[d] + red[d + 64] + red[d + 128] + red[d + 192];
}

// ---------------------------------------------------------------------------
// Full-precision monotonic float<->uint mapping (bijective, order-preserving).
// ---------------------------------------------------------------------------
__device__ __forceinline__ unsigned mono_pack(float s)
{
    unsigned b = __float_as_uint(s);
    return b ^ (unsigned)(((int)b >> 31) | 0x80000000);
}
__device__ __forceinline__ float mono_unpack(unsigned u)
{
    unsigned b = (u & 0x80000000u) ? (u ^ 0x80000000u) : ~u;
    return __uint_as_float(b);
}

// ---------------------------------------------------------------------------
// scores_kernel: 64 q-rows x 1024 keys per block, double-buffered k staging
// (one barrier per tile), LDG prefetch overlapping compute. Per warp 8 rows,
// 8x4 microtile/thread, qT broadcast. Scalar FFMA. 2 blocks/SM.
// ---------------------------------------------------------------------------
#define SROWS 64
#define QT_PITCH 66
#define KST_PITCH 132
#define SC_SMEM_BYTES ((64 * QT_PITCH + 2 * 64 * KST_PITCH) * 4)

__global__ __launch_bounds__(256, 2) void scores_kernel()
{
    extern __shared__ float sm[];
    float* qT  = sm;                    // [64][66]  qT[d][r]
    float* kst = qT + 64 * QT_PITCH;    // [2][64][132] kst[buf][d][m]

    int bh = blockIdx.y;
    int b = bh >> 3, h = bh & 7;
    int n0 = blockIdx.x * SROWS;
    int tid = threadIdx.x;
    int w    = tid >> 5;                // warp 0..7 -> rows 8w..8w+7
    int lane = tid & 31;                // cols 4*lane..4*lane+3 per tile
    const float scale = 0.125f;

    // load 64 q rows transposed (coalesced LDG)
    {
        size_t qbase = ((size_t)(b * N_ + n0)) * C_ + (size_t)h * D_;
        for (int f = tid; f < SROWS * 64; f += 256) {
            int r = f >> 6, d = f & 63;
            qT[d * QT_PITCH + r] = g_q[qbase + (size_t)r * C_ + d];
        }
    }

    size_t kbase = ((size_t)b * N_) * KV_C + (size_t)h * D_;
    size_t rowbase = ((size_t)bh * N_ + n0);

    // per-thread slice of a 128-key x 64-d tile: 8 float4
    // mapping g = tid + 256*i: m = g & 127, d4 = (g >> 7) * 4

    // prologue: load tile 0, stage into buf 0, prefetch tile 1
    float4 pf[8];
#pragma unroll
    for (int i = 0; i < 8; i++) {
        int g = tid + 256 * i;
        int m = g & 127, d4 = (g >> 7) * 4;
        pf[i] = *(const float4*)&g_kv[kbase + (size_t)m * KV_C + d4];
    }
#pragma unroll
    for (int i = 0; i < 8; i++) {
        int g = tid + 256 * i;
        int m = g & 127, d4 = (g >> 7) * 4;
        kst[(d4 + 0) * KST_PITCH + m] = pf[i].x;
        kst[(d4 + 1) * KST_PITCH + m] = pf[i].y;
        kst[(d4 + 2) * KST_PITCH + m] = pf[i].z;
        kst[(d4 + 3) * KST_PITCH + m] = pf[i].w;
    }
#pragma unroll
    for (int i = 0; i < 8; i++) {
        int g = tid + 256 * i;
        int m = g & 127, d4 = (g >> 7) * 4;
        pf[i] = *(const float4*)&g_kv[kbase + (size_t)(128 + m) * KV_C + d4];
    }
    __syncthreads();

    int cur = 0;
    for (int mt = 0; mt < N_; mt += 128) {
        float* kc = kst + cur * 64 * KST_PITCH;
        if (mt + 128 < N_) {
            // stage tile mt+128 into other buffer; prefetch mt+256
            float* kn = kst + (cur ^ 1) * 64 * KST_PITCH;
#pragma unroll
            for (int i = 0; i < 8; i++) {
                int g = tid + 256 * i;
                int m = g & 127, d4 = (g >> 7) * 4;
                kn[(d4 + 0) * KST_PITCH + m] = pf[i].x;
                kn[(d4 + 1) * KST_PITCH + m] = pf[i].y;
                kn[(d4 + 2) * KST_PITCH + m] = pf[i].z;
                kn[(d4 + 3) * KST_PITCH + m] = pf[i].w;
            }
            if (mt + 256 < N_) {
#pragma unroll
                for (int i = 0; i < 8; i++) {
                    int g = tid + 256 * i;
                    int m = g & 127, d4 = (g >> 7) * 4;
                    pf[i] = *(const float4*)&g_kv[kbase + (size_t)(mt + 256 + m) * KV_C + d4];
                }
            }
        }

        float acc[8][4];
#pragma unroll
        for (int r = 0; r < 8; r++)
#pragma unroll
            for (int c = 0; c < 4; c++) acc[r][c] = 0.f;

        const float* qTw = qT + 8 * w;          // even offset -> 8B aligned
#pragma unroll 4
        for (int d = 0; d < 64; d++) {
            float4 k4 = *(const float4*)&kc[d * KST_PITCH + 4 * lane];
            float2 q01 = *(const float2*)&qTw[d * QT_PITCH + 0];  // broadcast
            float2 q23 = *(const float2*)&qTw[d * QT_PITCH + 2];
            float2 q45 = *(const float2*)&qTw[d * QT_PITCH + 4];
            float2 q67 = *(const float2*)&qTw[d * QT_PITCH + 6];
            float q[8] = {q01.x, q01.y, q23.x, q23.y, q45.x, q45.y, q67.x, q67.y};
#pragma unroll
            for (int r = 0; r < 8; r++) {
                acc[r][0] += q[r] * k4.x; acc[r][1] += q[r] * k4.y;
                acc[r][2] += q[r] * k4.z; acc[r][3] += q[r] * k4.w;
            }
        }

#pragma unroll
        for (int r = 0; r < 8; r++) {
            uint4 p;
            p.x = mono_pack(acc[r][0] * scale);
            p.y = mono_pack(acc[r][1] * scale);
            p.z = mono_pack(acc[r][2] * scale);
            p.w = mono_pack(acc[r][3] * scale);
            *(uint4*)&g_su[(rowbase + 8 * w + r) * N_ + mt + 4 * lane] = p;
        }
        __syncthreads();
        cur ^= 1;
    }
}

// ---------------------------------------------------------------------------
// topk_kernel: 1 warp per score row, 8 rows/block, no smem. uint4 score
// loads, exact uint-argmax top-16 (indices/weights in registers, shfl
// broadcast), closed-form sparse softmax, float2 gather epilogue.
// ---------------------------------------------------------------------------
__global__ __launch_bounds__(256) void topk_kernel(const float* __restrict__ vs)
{
    size_t row = (size_t)blockIdx.x * 8 + (threadIdx.x >> 5);
    int lane = threadIdx.x & 31;
    int bh = (int)(row >> 10);
    int n  = (int)(row & 1023);
    int b = bh >> 3, h = bh & 7;

    const unsigned* srow = g_su + row * N_;

    // load 1024 scores as 8 uint4/lane; slot j=(i*4+c) <-> col 4*lane+128*i+c
    unsigned v[32];
#pragma unroll
    for (int i = 0; i < 8; i++) {
        uint4 p = *(const uint4*)&srow[4 * lane + 128 * i];
        v[4 * i + 0] = (p.x & ~31u) | (unsigned)(4 * i + 0);
        v[4 * i + 1] = (p.y & ~31u) | (unsigned)(4 * i + 1);
        v[4 * i + 2] = (p.z & ~31u) | (unsigned)(4 * i + 2);
        v[4 * i + 3] = (p.w & ~31u) | (unsigned)(4 * i + 3);
    }

    int selidx = 0;
#pragma unroll
    for (int it = 0; it < TOPK; it++) {
        unsigned lm = v[0];
#pragma unroll
        for (int j = 1; j < 32; j++) lm = max(lm, v[j]);
        unsigned gm = __reduce_max_sync(0xffffffffu, lm);
        unsigned ball = __ballot_sync(0xffffffffu, lm == gm);
        int wl = __ffs(ball) - 1;
        int jj = (int)(gm & 31u);
        if (lane == it)
            selidx = 4 * wl + 128 * (jj >> 2) + (jj & 3);
        if (lane == wl) {
#pragma unroll
            for (int j = 0; j < 32; j++)
                if (j == jj) v[j] = 0u;
        }
    }

    // exact-score closed-form sparse softmax
    float sv = 0.f;
    if (lane < TOPK) sv = mono_unpack(srow[selidx]);
    float s0 = __shfl_sync(0xffffffffu, sv, 0);
    float Mx = fmaxf(0.f, s0);
    float c  = expf(-Mx);
    float ww = (lane < TOPK) ? expf(sv - Mx) : 0.f;
    float s = ww;
#pragma unroll
    for (int off = 16; off; off >>= 1)
        s += __shfl_xor_sync(0xffffffffu, s, off);
    float Z = s + (float)(N_ - TOPK) * c;
    float wfin = (ww - c) / Z;
    float cz = c / Z;

    // gather epilogue: each lane owns d = {2*lane, 2*lane+1}
    size_t vbase = ((size_t)b * N_) * KV_C + C_ + (size_t)h * D_ + 2 * lane;
    float2 o = make_float2(0.f, 0.f);
#pragma unroll
    for (int i = 0; i < TOPK; i++) {
        float wi = __shfl_sync(0xffffffffu, wfin, i);
        int   ii = __shfl_sync(0xffffffffu, selidx, i);
        float2 vv = *(const float2*)&g_kv[vbase + (size_t)ii * KV_C];
        o.x += wi * vv.x; o.y += wi * vv.y;
    }
    float2 sv2 = *(const float2*)&vs[bh * 64 + 2 * lane];
    o.x += cz * sv2.x; o.y += cz * sv2.y;
    *(float2*)&g_att[((size_t)(b * N_ + n)) * C_ + (size_t)h * D_ + 2 * lane] = o;
}

// ---------------------------------------------------------------------------
extern "C" void kernel_launch(void* const* d_in, const int* in_sizes, int n_in,
                              void* d_out, int out_size)
{
    const float* x   = (const float*)d_in[0];
    const float* Wq  = (const float*)d_in[1];
    const float* bq  = (const float*)d_in[2];
    const float* Wkv = (const float*)d_in[3];
    const float* bkv = (const float*)d_in[4];
    const float* Wp  = (const float*)d_in[5];
    const float* bp  = (const float*)d_in[6];
    float* out = (float*)d_out;

    float *gq, *gkv, *gatt, *gvs;
    cudaGetSymbolAddress((void**)&gq,  g_q);
    cudaGetSymbolAddress((void**)&gkv, g_kv);
    cudaGetSymbolAddress((void**)&gatt, g_att);
    cudaGetSymbolAddress((void**)&gvs, g_vsum);

    // 1. Q = relu(x @ Wq + bq)
    gemm_kernel<true><<<dim3(C_ / 128, M_ / 128), 256>>>(x, Wq, bq, gq, C_, C_);
    // 2. KV = x @ Wkv + bkv
    gemm_kernel<false><<<dim3(KV_C / 128, M_ / 128), 256>>>(x, Wkv, bkv, gkv, C_, KV_C);
    // 3. vsum
    vsum_kernel<<<B_ * H_, 256>>>(gvs);
    // 4. scores GEMM -> packed global buffer
    cudaFuncSetAttribute(scores_kernel, cudaFuncAttributeMaxDynamicSharedMemorySize,
                         SC_SMEM_BYTES);
    scores_kernel<<<dim3(N_ / SROWS, B_ * H_), 256, SC_SMEM_BYTES>>>();
    // 5. top-16 + sparse softmax + gather
    topk_kernel<<<(int)(NROWS / 8), 256>>>(gvs);
    // 6. out = att @ Wp + bp
    gemm_kernel<false><<<dim3(C_ / 128, M_ / 128), 256>>>(gatt, Wp, bp, out, C_, C_);
}